// round 12
// baseline (speedup 1.0000x reference)
#include <cuda_runtime.h>
#include <math.h>
#include <stdint.h>

// Problem constants
#define B_  4
#define N_  2048
#define D_  1024
#define E_  16
#define C_  256
#define BNEC_ (4LL * 2048 * 16 * 256)   // 33,554,432 elements per output tensor
#define FLT_MIN_NORMAL 1.17549435082228750797e-38f  // 2^-126

#define NLOG  512          // logits blocks: 2 halves x 256, 1 token/warp
#define NFILL 1024         // fill blocks
#define NTOPK 64           // one per (b,e), last in grid
#define NTOT  (NLOG + NFILL + NTOPK)
#define HALF_OFF (B_ * E_ * N_)

// Partial logits [half][b][e][n] (raw dots; topk applies /exp(temp))
__device__ float g_plog[2 * B_ * E_ * N_];
// Cross-block dependency flags (reset by the last topk block each launch,
// so graph replays are deterministic).
__device__ volatile int g_log_done;
__device__ volatile int g_fill_done;
__device__ int g_reset_cnt;

// ---------------------------------------------------------------------------
// ONE kernel, three block roles.
//  * blocks [0,1536) interleaved 1:2  -> logits (512) : fill (1024)
//  * blocks [1536,1600)              -> topk+scatter, gated on flag counters
// Fill writes 268MB with streaming stores (DRAM roofline ~49us, measured).
// Logits hide under it. Topk blocks are scheduled last; their softmax+sort
// needs only g_plog (ready early) and overlaps the fill tail; only the final
// scatter waits for the fill counter. This removes the old K2's serial
// 9.5-10.7us (DRAM idle at 1.4% during it) from the critical path.
// ---------------------------------------------------------------------------
__global__ __launch_bounds__(1024, 1) void fused_all_kernel(
        const float* __restrict__ key,
        const float* __restrict__ query,
        const float* __restrict__ temp,
        float* __restrict__ out, long long out_n) {
    __shared__ __align__(16) unsigned char sm[35 * 1024];   // role-dependent
    const int bid  = blockIdx.x;
    const int tid  = threadIdx.x;
    const int lane = tid & 31;
    const int warp = tid >> 5;

    if (bid < NLOG + NFILL) {
        if ((bid % 3) == 0) {
            // ================= logits role =================
            float* sq = (float*)sm;                            // 32 KB
            float (*tile)[33] = (float(*)[33])(sm + 32768);
            const int lid  = bid / 3;           // 0..511
            const int half = lid >> 8;          // dim half 0/1
            const int tok  = (lid & 255) * 32 + warp;          // 1 token/warp

            const float4* kp =
                (const float4*)(key + (long long)tok * D_ + half * 512);
            float4 kv = kp[lane], kvn;

            for (int i = tid; i < E_ * 512; i += 1024) {
                int e = i >> 9, j = i & 511;
                sq[i] = query[e * D_ + half * 512 + j];
            }
            __syncthreads();

            float acc[E_];
            #pragma unroll
            for (int e = 0; e < E_; e++) acc[e] = 0.f;

            const float4* sq4 = (const float4*)sq;
            #pragma unroll
            for (int i = 0; i < 4; ++i) {
                if (i < 3) kvn = kp[lane + 32 * (i + 1)];
                int dv = lane + 32 * i;
                #pragma unroll
                for (int e = 0; e < E_; ++e) {
                    float4 q = sq4[e * 128 + dv];
                    acc[e] += kv.x * q.x;
                    acc[e] += kv.y * q.y;
                    acc[e] += kv.z * q.z;
                    acc[e] += kv.w * q.w;
                }
                kv = kvn;
            }

            #pragma unroll
            for (int e = 0; e < E_; ++e) {
                float v = acc[e];
                #pragma unroll
                for (int off = 16; off > 0; off >>= 1)
                    v += __shfl_xor_sync(0xffffffffu, v, off);
                if (lane == 0) tile[e][warp] = v;
            }
            __syncthreads();

            if (tid < 512) {   // coalesced 128B segments per expert row
                int base = (lid & 255) * 32;
                int b = base >> 11, n0 = base & (N_ - 1);
                int e = tid >> 5, tk = tid & 31;
                g_plog[half * HALF_OFF + (b * E_ + e) * N_ + n0 + tk] =
                    tile[e][tk];
            }
            __threadfence();
            __syncthreads();
            if (tid == 0) atomicAdd((int*)&g_log_done, 1);
        } else {
            // ================= fill role =================
            int fid = 2 * (bid / 3) + (bid % 3) - 1;   // 0..1023
            long long n4 = out_n >> 2;
            float4* o4 = (float4*)out;
            long long i = (long long)fid * 1024 + tid;
            long long stride = (long long)NFILL * 1024;
            float4 z = make_float4(0.f, 0.f, 0.f, 0.f);
            for (long long k = i; k < n4; k += stride) __stcs(&o4[k], z);
            if (fid == 0) {
                long long tail = n4 << 2;
                if (tid < out_n - tail) out[tail + tid] = 0.f;
            }
            __threadfence();
            __syncthreads();
            if (tid == 0) atomicAdd((int*)&g_fill_done, 1);
        }
        return;
    }

    // ================= topk + scatter role =================
    unsigned long long* sk = (unsigned long long*)sm;     // 16 KB
    float* red  = (float*)(sm + 16384);
    int*   scnt = (int*)(sm + 16512);
    int*   sbase= (int*)(sm + 16768);
    int*   mPtr = (int*)(sm + 17024);

    const int be = bid - (NLOG + NFILL);      // 0..63
    const int b = be / E_, e = be - b * E_;

    // Wait for all logits blocks.
    if (tid == 0) { while (g_log_done < NLOG) __nanosleep(128); }
    __syncthreads();
    __threadfence();

    const float* rowA = g_plog + (long long)be * N_;
    const float* rowB = rowA + HALF_OFF;
    const float et = expf(temp[0]);
    float x0 = (rowA[tid] + rowB[tid]) / et;
    float x1 = (rowA[tid + 1024] + rowB[tid + 1024]) / et;

    // ---- block max ----
    float m = fmaxf(x0, x1);
    #pragma unroll
    for (int off = 16; off > 0; off >>= 1)
        m = fmaxf(m, __shfl_xor_sync(0xffffffffu, m, off));
    if (lane == 0) red[warp] = m;
    __syncthreads();
    if (tid < 32) {
        float v = red[tid];
        #pragma unroll
        for (int off = 16; off > 0; off >>= 1)
            v = fmaxf(v, __shfl_xor_sync(0xffffffffu, v, off));
        if (tid == 0) red[0] = v;
    }
    __syncthreads();
    m = red[0];
    __syncthreads();

    // ---- exp + sum ----
    float e0 = expf(x0 - m), e1 = expf(x1 - m);
    float s = e0 + e1;
    #pragma unroll
    for (int off = 16; off > 0; off >>= 1)
        s += __shfl_xor_sync(0xffffffffu, s, off);
    if (lane == 0) red[warp] = s;
    __syncthreads();
    if (tid < 32) {
        float v = red[tid];
        #pragma unroll
        for (int off = 16; off > 0; off >>= 1)
            v += __shfl_xor_sync(0xffffffffu, v, off);
        if (tid == 0) red[0] = v;
    }
    __syncthreads();
    const float S = red[0];

    // ---- normalize (ftz: subnormal affinity -> 0, XLA tie semantics) ----
    float a0 = e0 / S; if (a0 < FLT_MIN_NORMAL) a0 = 0.f;
    float a1 = e1 / S; if (a1 < FLT_MIN_NORMAL) a1 = 0.f;
    const bool z0 = (a0 == 0.f), z1 = (a1 == 0.f);

    unsigned bal0 = __ballot_sync(0xffffffffu, z0);
    unsigned bal1 = __ballot_sync(0xffffffffu, z1);
    if (lane == 0) { scnt[warp] = __popc(bal0); scnt[32 + warp] = __popc(bal1); }
    if (tid < C_) sk[tid] = 0ull;           // pad (zero-keys sort to tail)
    __syncthreads();

    // ---- one-warp exclusive scan over the 64 ordered chunks ----
    if (tid < 32) {
        int c0 = scnt[tid], c1 = scnt[tid + 32];
        int s0 = c0;
        #pragma unroll
        for (int off = 1; off < 32; off <<= 1) {
            int v = __shfl_up_sync(0xffffffffu, s0, off);
            if (tid >= off) s0 += v;
        }
        int tot0 = __shfl_sync(0xffffffffu, s0, 31);
        int s1 = c1;
        #pragma unroll
        for (int off = 1; off < 32; off <<= 1) {
            int v = __shfl_up_sync(0xffffffffu, s1, off);
            if (tid >= off) s1 += v;
        }
        sbase[tid] = s0 - c0;
        sbase[tid + 32] = tot0 + s1 - c1;
        if (tid == 31) *mPtr = 2048 - (tot0 + s1);   // # nonzero affinities
    }
    __syncthreads();
    const int mNZ = *mPtr;
    const unsigned lmask = (1u << lane) - 1u;
    const int zr0 = sbase[warp]      + __popc(bal0 & lmask);
    const int zr1 = sbase[32 + warp] + __popc(bal1 & lmask);

    const bool hasC = (out_n >= 2 * BNEC_);

    if (mNZ <= C_) {
        // ---- compact nonzeros (packed (valbits<<32)|(2047-idx)) ----
        if (!z0) {
            int r = tid - zr0;
            sk[r] = ((unsigned long long)__float_as_uint(a0) << 32)
                  | (unsigned long long)(2047 - tid);
        }
        if (!z1) {
            int r = (tid + 1024) - zr1;
            sk[r] = ((unsigned long long)__float_as_uint(a1) << 32)
                  | (unsigned long long)(2047 - (tid + 1024));
        }
        __syncthreads();

        // ---- fixed 256-key bitonic sort, descending (round-9 best) ----
        // Overlaps with the fill tail — no out-writes yet.
        if (tid < 128) {
            for (int k = 2; k <= 256; k <<= 1) {
                for (int j = k >> 1; j > 0; j >>= 1) {
                    int i = 2 * tid - (tid & (j - 1));
                    int l = i + j;
                    unsigned long long A = sk[i], Bv = sk[l];
                    bool dir = ((i & k) == 0);
                    bool sw  = dir ? (A < Bv) : (A > Bv);
                    if (sw) { sk[i] = Bv; sk[l] = A; }
                    asm volatile("bar.sync 1, 128;" ::: "memory");
                }
            }
        }
        __syncthreads();

        // ---- wait for the fill, then ALL output writes ----
        if (tid == 0) { while (g_fill_done < NFILL) __nanosleep(128); }
        __syncthreads();
        __threadfence();

        if (z0 && zr0 < C_ - mNZ) {
            long long off = (((long long)b * N_ + tid) * E_ + e) * C_ + (mNZ + zr0);
            out[off] = 1.0f;                 // combine = 0 (already zeroed)
        }
        if (z1 && zr1 < C_ - mNZ) {
            long long off = (((long long)b * N_ + (tid + 1024)) * E_ + e) * C_
                          + (mNZ + zr1);
            out[off] = 1.0f;
        }
        if (tid < mNZ) {
            unsigned long long K = sk[tid];
            int   n = 2047 - (int)(K & 0x7FFu);
            float v = __uint_as_float((unsigned int)(K >> 32));
            long long off = (((long long)b * N_ + n) * E_ + e) * C_ + tid;
            out[off] = 1.0f;
            if (hasC) out[BNEC_ + off] = v;
        }
    } else {
        // ---- fallback (m > 256): full 2048-key bitonic sort ----
        sk[tid]        = ((unsigned long long)__float_as_uint(a0) << 32)
                       | (unsigned long long)(2047 - tid);
        sk[tid + 1024] = ((unsigned long long)__float_as_uint(a1) << 32)
                       | (unsigned long long)(2047 - (tid + 1024));
        __syncthreads();
        for (int k = 2; k <= N_; k <<= 1) {
            for (int j = k >> 1; j > 0; j >>= 1) {
                int i = 2 * tid - (tid & (j - 1));
                int l = i + j;
                unsigned long long A = sk[i], Bv = sk[l];
                bool dir = ((i & k) == 0);
                bool sw  = dir ? (A < Bv) : (A > Bv);
                if (sw) { sk[i] = Bv; sk[l] = A; }
                __syncthreads();
            }
        }
        if (tid == 0) { while (g_fill_done < NFILL) __nanosleep(128); }
        __syncthreads();
        __threadfence();
        if (tid < C_) {
            unsigned long long K = sk[tid];
            int   n = 2047 - (int)(K & 0x7FFu);
            float v = __uint_as_float((unsigned int)(K >> 32));
            long long off = (((long long)b * N_ + n) * E_ + e) * C_ + tid;
            out[off] = 1.0f;
            if (hasC) out[BNEC_ + off] = v;
        }
    }

    // ---- last topk block resets flags for the next (graph) launch ----
    __syncthreads();
    if (tid == 0) {
        int d = atomicAdd(&g_reset_cnt, 1);
        if (d == NTOPK - 1) {
            g_log_done = 0;
            g_fill_done = 0;
            g_reset_cnt = 0;
        }
    }
}

// ---------------------------------------------------------------------------
extern "C" void kernel_launch(void* const* d_in, const int* in_sizes, int n_in,
                              void* d_out, int out_size) {
    const float* key = nullptr; const float* query = nullptr; const float* temp = nullptr;
    for (int i = 0; i < n_in; ++i) {
        if (in_sizes[i] == B_ * N_ * D_)      key   = (const float*)d_in[i];
        else if (in_sizes[i] == E_ * D_)      query = (const float*)d_in[i];
        else if (in_sizes[i] == 1)            temp  = (const float*)d_in[i];
    }
    if (!key)   key   = (const float*)d_in[0];
    if (!query) query = (const float*)d_in[1];
    if (!temp)  temp  = (const float*)d_in[2];
    float* out = (float*)d_out;

    fused_all_kernel<<<NTOT, 1024>>>(key, query, temp, out, (long long)out_size);
}

// round 13
// speedup vs baseline: 1.4714x; 1.4714x over previous
#include <cuda_runtime.h>
#include <math.h>
#include <stdint.h>

// Problem constants
#define B_  4
#define N_  2048
#define D_  1024
#define E_  16
#define C_  256
#define BNEC_ (4LL * 2048 * 16 * 256)   // 33,554,432 elements per output tensor
#define FLT_MIN_NORMAL 1.17549435082228750797e-38f  // 2^-126

#define NLOG_BLOCKS 1024         // 2 halves x 512 (2 tokens/warp)
#define NZERO_BLOCKS 4096
#define NTOT_BLOCKS (NLOG_BLOCKS + NZERO_BLOCKS)
#define HALF_OFF (B_ * E_ * N_)

// Partial logits: [half][b][e][n] (raw dots; K2 applies /exp(temp))
__device__ float g_plog[2 * B_ * E_ * N_];

// ---------------------------------------------------------------------------
// Kernel 1 (round-9 proven structure): among blocks [0,4096), every 4th block
// is a logits block (1024 total); the rest plus [4096,5120) are fill blocks
// using streaming (__stcs) float4 stores — measured best (K1 ~49.2us, at the
// DRAM write roofline). 64-reg cap keeps fill occupancy at 4 blocks/SM.
// ---------------------------------------------------------------------------
__global__ __launch_bounds__(256, 4) void fused_zero_logits_kernel(
        const float* __restrict__ key,
        const float* __restrict__ query,
        float* __restrict__ out, long long out_n) {
    __shared__ float sq[E_ * 512];   // 32 KB: 16 experts x 512 dims (this half)
    __shared__ float tile[E_][17];   // transpose tile for coalesced writes

    const int bx = blockIdx.x;
    const bool is_logits = (bx < 4096) && ((bx & 3) == 0);

    if (!is_logits) {
        // ---------------- zero-fill path (streaming stores) ----------------
        int fid = (bx < 4096) ? (3 * (bx >> 2) + (bx & 3) - 1)
                              : (3072 + (bx - 4096));
        long long n4 = out_n >> 2;
        float4* o4 = reinterpret_cast<float4*>(out);
        long long i = (long long)fid * 256 + threadIdx.x;
        long long stride = (long long)NZERO_BLOCKS * 256;
        float4 z = make_float4(0.f, 0.f, 0.f, 0.f);
        for (long long k = i; k < n4; k += stride) __stcs(&o4[k], z);
        long long tail = n4 << 2;
        if (i < out_n - tail) out[tail + i] = 0.f;
        return;
    }

    // ---------------- logits path (2 tokens per warp) ----------------
    const int lid_blk = bx >> 2;                          // 0..1023
    const int lane = threadIdx.x & 31;
    const int warp = threadIdx.x >> 5;
    const int half = lid_blk >> 9;                        // dim half 0/1
    const int tok0 = ((lid_blk & 511) * 8 + warp) * 2;

    // Prefetch i=0 key vectors BEFORE the staging sync.
    const float4* kp[2];
    #pragma unroll
    for (int t = 0; t < 2; ++t)
        kp[t] = reinterpret_cast<const float4*>(
                    key + (long long)(tok0 + t) * D_ + half * 512);
    float4 kv[2], kvn[2];
    #pragma unroll
    for (int t = 0; t < 2; ++t) kv[t] = kp[t][lane];

    // Stage this half of query.
    for (int i = threadIdx.x; i < E_ * 512; i += 256) {
        int e = i >> 9, j = i & 511;
        sq[i] = query[e * D_ + half * 512 + j];
    }
    __syncthreads();

    float acc[2][E_];
    #pragma unroll
    for (int t = 0; t < 2; t++)
        #pragma unroll
        for (int e = 0; e < E_; e++) acc[t][e] = 0.f;

    const float4* sq4 = reinterpret_cast<const float4*>(sq);
    #pragma unroll
    for (int i = 0; i < 4; ++i) {
        if (i < 3) {
            int dvn = lane + 32 * (i + 1);
            #pragma unroll
            for (int t = 0; t < 2; ++t) kvn[t] = kp[t][dvn];
        }
        int dv = lane + 32 * i;
        #pragma unroll
        for (int e = 0; e < E_; ++e) {
            float4 q = sq4[e * 128 + dv];
            #pragma unroll
            for (int t = 0; t < 2; ++t) {
                acc[t][e] += kv[t].x * q.x;
                acc[t][e] += kv[t].y * q.y;
                acc[t][e] += kv[t].z * q.z;
                acc[t][e] += kv[t].w * q.w;
            }
        }
        #pragma unroll
        for (int t = 0; t < 2; ++t) kv[t] = kvn[t];
    }

    // Warp-reduce into the transpose tile (block covers 16 contiguous tokens).
    #pragma unroll
    for (int t = 0; t < 2; ++t) {
        #pragma unroll
        for (int e = 0; e < E_; ++e) {
            float v = acc[t][e];
            #pragma unroll
            for (int off = 16; off > 0; off >>= 1)
                v += __shfl_xor_sync(0xffffffffu, v, off);
            if (lane == 0) tile[e][warp * 2 + t] = v;
        }
    }
    __syncthreads();

    // Coalesced write: threads 0-15 of each expert row write 16 consecutive
    // floats (64B segment).
    {
        int base = (lid_blk & 511) * 16;      // first token of this block
        int b = base >> 11, n0 = base & (N_ - 1);
        int e = threadIdx.x >> 4, tk = threadIdx.x & 15;
        g_plog[half * HALF_OFF + (b * E_ + e) * N_ + n0 + tk] = tile[e][tk];
    }
}

// ---------------------------------------------------------------------------
// Kernel 2: per (b,e) row — softmax (ftz on subnormal affinities, matching
// XLA semantics), then SELECT-then-RANK (no sort!):
//   * nonzero affinities (count m, typically ~50) compact in index order into
//     sk[] as packed keys (valbits<<32)|(2047-idx); keys are UNIQUE;
//   * thread t < m computes rank_t = #{j : key_j > key_t} by scanning the m
//     keys (broadcast LDS, zero barriers) — rank order == (value desc, index
//     asc) == jax.lax.top_k order, bit-identical to a descending sort;
//   * thread t scatters dispatch=1.0 / combine=value into slot rank_t;
//   * slots [m,256) are zero-affinity tokens in ascending index order, written
//     directly from a ballot prefix-scan (dispatch=1.0, combine=0 already).
// Fallback to a full 2048 bitonic sort if m > 256 (not expected).
// ---------------------------------------------------------------------------
__global__ __launch_bounds__(1024) void topk_scatter_kernel(
        const float* __restrict__ temp,
        float* __restrict__ out, long long out_n) {
    __shared__ unsigned long long sk[N_];   // full array only used in fallback
    __shared__ float red[32];
    __shared__ int scnt[64], sbase[64];
    __shared__ int mTot;

    const int be  = blockIdx.x;           // 0..63
    const int b = be / E_, e = be - b * E_;
    const float* rowA = g_plog + (long long)be * N_;
    const float* rowB = rowA + HALF_OFF;
    const int t = threadIdx.x;
    const int lane = t & 31, w = t >> 5;
    const float et = expf(temp[0]);

    float x0 = (rowA[t] + rowB[t]) / et;
    float x1 = (rowA[t + 1024] + rowB[t + 1024]) / et;

    // ---- block max ----
    float m = fmaxf(x0, x1);
    #pragma unroll
    for (int off = 16; off > 0; off >>= 1)
        m = fmaxf(m, __shfl_xor_sync(0xffffffffu, m, off));
    if (lane == 0) red[w] = m;
    __syncthreads();
    if (t < 32) {
        float v = red[t];
        #pragma unroll
        for (int off = 16; off > 0; off >>= 1)
            v = fmaxf(v, __shfl_xor_sync(0xffffffffu, v, off));
        if (t == 0) red[0] = v;
    }
    __syncthreads();
    m = red[0];
    __syncthreads();

    // ---- exp + sum ----
    float e0 = expf(x0 - m), e1 = expf(x1 - m);
    float s = e0 + e1;
    #pragma unroll
    for (int off = 16; off > 0; off >>= 1)
        s += __shfl_xor_sync(0xffffffffu, s, off);
    if (lane == 0) red[w] = s;
    __syncthreads();
    if (t < 32) {
        float v = red[t];
        #pragma unroll
        for (int off = 16; off > 0; off >>= 1)
            v += __shfl_xor_sync(0xffffffffu, v, off);
        if (t == 0) red[0] = v;
    }
    __syncthreads();
    const float S = red[0];

    // ---- normalize (ftz) ----
    float a0 = e0 / S; if (a0 < FLT_MIN_NORMAL) a0 = 0.f;
    float a1 = e1 / S; if (a1 < FLT_MIN_NORMAL) a1 = 0.f;
    const bool z0 = (a0 == 0.f), z1 = (a1 == 0.f);

    unsigned bal0 = __ballot_sync(0xffffffffu, z0);
    unsigned bal1 = __ballot_sync(0xffffffffu, z1);
    if (lane == 0) { scnt[w] = __popc(bal0); scnt[32 + w] = __popc(bal1); }
    __syncthreads();

    // ---- one-warp exclusive scan over the 64 ordered chunks ----
    if (t < 32) {
        int c0 = scnt[t], c1 = scnt[t + 32];
        int s0 = c0;
        #pragma unroll
        for (int off = 1; off < 32; off <<= 1) {
            int v = __shfl_up_sync(0xffffffffu, s0, off);
            if (t >= off) s0 += v;
        }
        int tot0 = __shfl_sync(0xffffffffu, s0, 31);
        int s1 = c1;
        #pragma unroll
        for (int off = 1; off < 32; off <<= 1) {
            int v = __shfl_up_sync(0xffffffffu, s1, off);
            if (t >= off) s1 += v;
        }
        sbase[t] = s0 - c0;
        sbase[t + 32] = tot0 + s1 - c1;
        if (t == 31) mTot = 2 * 1024 - (tot0 + s1);   // # nonzero affinities
    }
    __syncthreads();
    const int mNZ = mTot;
    const unsigned lmask = (1u << lane) - 1u;
    const int zr0 = sbase[w]      + __popc(bal0 & lmask);   // zeros before idx t
    const int zr1 = sbase[32 + w] + __popc(bal1 & lmask);   // zeros before idx t+1024

    const bool hasC = (out_n >= 2 * BNEC_);

    if (mNZ <= C_) {
        // ---- compact nonzeros (index order) ----
        if (!z0) {
            int r = t - zr0;
            sk[r] = ((unsigned long long)__float_as_uint(a0) << 32)
                  | (unsigned long long)(2047 - t);
        }
        if (!z1) {
            int r = (t + 1024) - zr1;
            sk[r] = ((unsigned long long)__float_as_uint(a1) << 32)
                  | (unsigned long long)(2047 - (t + 1024));
        }
        // ---- zero-affinity fill: slot c = m + zero_rank (index ascending) ----
        if (z0 && zr0 < C_ - mNZ) {
            long long off = (((long long)b * N_ + t) * E_ + e) * C_ + (mNZ + zr0);
            out[off] = 1.0f;                 // combine = 0, already zeroed
        }
        if (z1 && zr1 < C_ - mNZ) {
            long long off = (((long long)b * N_ + (t + 1024)) * E_ + e) * C_ + (mNZ + zr1);
            out[off] = 1.0f;
        }
        __syncthreads();

        // ---- rank-by-counting over the m unique keys (no barriers) ----
        if (t < mNZ) {
            unsigned long long K = sk[t];
            int rank = 0;
            for (int j = 0; j < mNZ; ++j)
                rank += (sk[j] > K);
            int   n = 2047 - (int)(K & 0x7FFu);
            float v = __uint_as_float((unsigned int)(K >> 32));
            long long off = (((long long)b * N_ + n) * E_ + e) * C_ + rank;
            out[off] = 1.0f;
            if (hasC) out[BNEC_ + off] = v;
        }
    } else {
        // ---- fallback (m > 256): full 2048-key bitonic sort ----
        sk[t]        = ((unsigned long long)__float_as_uint(a0) << 32)
                     | (unsigned long long)(2047 - t);
        sk[t + 1024] = ((unsigned long long)__float_as_uint(a1) << 32)
                     | (unsigned long long)(2047 - (t + 1024));
        __syncthreads();
        for (int k = 2; k <= N_; k <<= 1) {
            for (int j = k >> 1; j > 0; j >>= 1) {
                int i = 2 * t - (t & (j - 1));
                int l = i + j;
                unsigned long long A = sk[i], Bv = sk[l];
                bool dir = ((i & k) == 0);
                bool sw  = dir ? (A < Bv) : (A > Bv);
                if (sw) { sk[i] = Bv; sk[l] = A; }
                __syncthreads();
            }
        }
        if (t < C_) {
            unsigned long long K = sk[t];
            int   n = 2047 - (int)(K & 0x7FFu);
            float v = __uint_as_float((unsigned int)(K >> 32));
            long long off = (((long long)b * N_ + n) * E_ + e) * C_ + t;
            out[off] = 1.0f;
            if (hasC) out[BNEC_ + off] = v;
        }
    }
}

// ---------------------------------------------------------------------------
extern "C" void kernel_launch(void* const* d_in, const int* in_sizes, int n_in,
                              void* d_out, int out_size) {
    const float* key = nullptr; const float* query = nullptr; const float* temp = nullptr;
    for (int i = 0; i < n_in; ++i) {
        if (in_sizes[i] == B_ * N_ * D_)      key   = (const float*)d_in[i];
        else if (in_sizes[i] == E_ * D_)      query = (const float*)d_in[i];
        else if (in_sizes[i] == 1)            temp  = (const float*)d_in[i];
    }
    if (!key)   key   = (const float*)d_in[0];
    if (!query) query = (const float*)d_in[1];
    if (!temp)  temp  = (const float*)d_in[2];
    float* out = (float*)d_out;

    // K1: streaming zero-fill (268 MB, DRAM roofline) + interleaved logits.
    fused_zero_logits_kernel<<<NTOT_BLOCKS, 256>>>(
        key, query, out, (long long)out_size);
    // K2: softmax + select-then-RANK top-256 + direct scatter.
    topk_scatter_kernel<<<B_ * E_, 1024>>>(temp, out, (long long)out_size);
}